// round 11
// baseline (speedup 1.0000x reference)
#include <cuda_runtime.h>
#include <cuda_fp16.h>
#include <cstdint>

#define BB  4
#define SS  2048
#define DD  1024
#define HH  16
#define DKK 64
#define NN  (BB*SS)
#define NND (NN*DD)             // 8388608
#define WSZ (DD*DD)

// ---- fp16x3 warp-MMA GEMM tiling ----
#define BM   128
#define BN   128
#define BK   32                 // 32 halves = 16 half2 words per row per chunk
#define NIT  (DD/BK)            // 32
#define RS   20                 // smem row stride in half2-word units
#define PLANE (BM*RS)           // 2560 words
#define STAGEF (4*PLANE)        // Ahi,Alo,Bhi,Blo
#define GEMM_SMEM (2*STAGEF*4)  // 81920 bytes

// ---- attention tiling ----
#define TQ   128
#define TKV  64
#define K36  36
#define PSOFF 9216
#define ATTN_SMEM ((4*64*K36 + 128*K36)*4)   // 55296 bytes

// scratch
__device__ __half g_xh[3*NND];   // split activations hi (Q,K,V; plane0 reused for concat)
__device__ __half g_xl[3*NND];
__device__ __half g_wh[4*WSZ];   // split weights hi (Wq^T,Wk^T,Wv^T,Wo)
__device__ __half g_wl[4*WSZ];
__device__ float  g_q[NND];      // [B,S,H,DK]
__device__ float  g_k[NND];
__device__ float  g_v[NND];
__device__ float  g_c[NND];

__device__ __forceinline__ uint32_t smem_u32(const void* p) {
    uint32_t a;
    asm("{ .reg .u64 t; cvta.to.shared.u64 t, %1; cvt.u32.u64 %0, t; }" : "=r"(a) : "l"(p));
    return a;
}
__device__ __forceinline__ void ldm4(uint32_t* r, uint32_t a) {
    asm volatile("ldmatrix.sync.aligned.m8n8.x4.shared.b16 {%0,%1,%2,%3}, [%4];"
        : "=r"(r[0]), "=r"(r[1]), "=r"(r[2]), "=r"(r[3]) : "r"(a));
}
__device__ __forceinline__ void cpa16(uint32_t s, const void* g) {
    asm volatile("cp.async.cg.shared.global [%0], [%1], 16;" :: "r"(s), "l"(g));
}
__device__ __forceinline__ void cpa_commit() {
    asm volatile("cp.async.commit_group;" ::: "memory");
}

// split 8 consecutive fp32 (two float4) into half2-packed hi/lo uint4s
__device__ __forceinline__ void split8(float4 p, float4 q, uint4& hi, uint4& lo) {
    __half2 h0 = __floats2half2_rn(p.x, p.y);
    __half2 h1 = __floats2half2_rn(p.z, p.w);
    __half2 h2v = __floats2half2_rn(q.x, q.y);
    __half2 h3 = __floats2half2_rn(q.z, q.w);
    float2 f0 = __half22float2(h0), f1 = __half22float2(h1);
    float2 f2 = __half22float2(h2v), f3 = __half22float2(h3);
    __half2 l0 = __floats2half2_rn(p.x - f0.x, p.y - f0.y);
    __half2 l1 = __floats2half2_rn(p.z - f1.x, p.w - f1.y);
    __half2 l2 = __floats2half2_rn(q.x - f2.x, q.y - f2.y);
    __half2 l3 = __floats2half2_rn(q.z - f3.x, q.w - f3.y);
    hi = make_uint4(*(uint32_t*)&h0, *(uint32_t*)&h1, *(uint32_t*)&h2v, *(uint32_t*)&h3);
    lo = make_uint4(*(uint32_t*)&l0, *(uint32_t*)&l1, *(uint32_t*)&l2, *(uint32_t*)&l3);
}

__device__ __forceinline__ void mma16(float* d, const uint32_t* a, uint32_t b0, uint32_t b1) {
    asm volatile("mma.sync.aligned.m16n8k16.row.col.f32.f16.f16.f32 "
        "{%0,%1,%2,%3},{%4,%5,%6,%7},{%8,%9},{%0,%1,%2,%3};"
        : "+f"(d[0]), "+f"(d[1]), "+f"(d[2]), "+f"(d[3])
        : "r"(a[0]), "r"(a[1]), "r"(a[2]), "r"(a[3]), "r"(b0), "r"(b1));
}

// ---------------------------------------------------------------------------
// split fp32 array into fp16 hi/lo planes (8 floats per thread)
// ---------------------------------------------------------------------------
__global__ void split_half(const float4* __restrict__ X, uint4* __restrict__ hi,
                           uint4* __restrict__ lo, int n8)
{
    int i = blockIdx.x * blockDim.x + threadIdx.x;
    if (i < n8) {
        uint4 h, l;
        split8(X[2*i], X[2*i+1], h, l);
        hi[i] = h; lo[i] = l;
    }
}

// ---------------------------------------------------------------------------
// Weight transpose + fp16 split: Wh/Wl[h*64+dk][d] = split(W[h][d][dk])
// ---------------------------------------------------------------------------
__global__ void transpose_split_w(const float* __restrict__ W,
                                  __half* __restrict__ Wh, __half* __restrict__ Wl)
{
    __shared__ float t[32][33];
    const int h  = blockIdx.z;
    const int d0 = blockIdx.y << 5;
    const int k0 = blockIdx.x << 5;
    const int c  = threadIdx.x & 31;
    const int r4 = threadIdx.x >> 5;
    const float* Whp = W + ((size_t)h << 16);
    #pragma unroll
    for (int i = 0; i < 4; i++)
        t[r4 + 8*i][c] = Whp[(size_t)(d0 + r4 + 8*i) * DKK + k0 + c];
    __syncthreads();
    const size_t ob = (size_t)(h * DKK + k0) * DD + d0;
    #pragma unroll
    for (int i = 0; i < 4; i++) {
        float v = t[c][r4 + 8*i];
        __half hv = __float2half_rn(v);
        __half lv = __float2half_rn(v - __half2float(hv));
        Wh[ob + (size_t)(r4 + 8*i) * DD + c] = hv;
        Wl[ob + (size_t)(r4 + 8*i) * DD + c] = lv;
    }
}

// ---------------------------------------------------------------------------
// fp16x3 warp-MMA GEMM on pre-split fp16 planes, cp.async 2-stage, ldmatrix.
// N-segment fusion: seg = n0g/1024 selects A plane and C.
// ---------------------------------------------------------------------------
__global__ __launch_bounds__(256, 2)
void gemm_fp16(const __half* __restrict__ Ahb, const __half* __restrict__ Alb,
               const __half* __restrict__ Bh, const __half* __restrict__ Bl,
               const float* __restrict__ bias,
               float* __restrict__ C0, float* __restrict__ C1, float* __restrict__ C2)
{
    extern __shared__ float sm[];
    const uint32_t smb = smem_u32(sm);
    const int tid  = threadIdx.x;
    const int m0   = blockIdx.y * BM;
    const int n0g  = blockIdx.x * BN;
    const int seg  = n0g >> 10;
    const int n0   = n0g & (DD - 1);
    const __half* Ah = Ahb + (size_t)seg * NND;
    const __half* Al = Alb + (size_t)seg * NND;
    float*        C  = (seg == 0) ? C0 : (seg == 1) ? C1 : C2;

    const int w    = tid >> 5, lane = tid & 31;
    const int grp  = lane >> 2, tig = lane & 3;
    const int m_off = (w >> 2) * 64;
    const int n_off = (w & 3) * 32;

    // ldmatrix lane->address components (half2-word units)
    const int a_row = lane & 15;
    const int a_k   = (lane >> 4) * 4;
    const int b_row = (lane & 7) + ((lane >> 1) & 8);
    const int b_k   = ((lane >> 3) & 1) * 4;

    // cp.async loader: thread -> (row, half-row)
    const int lrow = tid >> 1, lqh = tid & 1;   // lqh*8 word offset

    float acc[4][4][4];
    #pragma unroll
    for (int t = 0; t < 4; t++)
        #pragma unroll
        for (int u = 0; u < 4; u++)
            #pragma unroll
            for (int q = 0; q < 4; q++) acc[t][u][q] = 0.f;

    #define ISSUE(k0idx, buf)                                                      \
    {                                                                              \
        const int kk0 = (k0idx) * BK;                                              \
        const uint32_t st = smb + (uint32_t)(buf) * (STAGEF * 4u);                 \
        const uint32_t dw = st + (uint32_t)(lrow * RS + lqh * 8) * 4u;             \
        const __half* pah = Ah + (size_t)(m0 + lrow) * DD + kk0 + lqh * 16;        \
        const __half* pal = Al + (size_t)(m0 + lrow) * DD + kk0 + lqh * 16;        \
        const __half* pbh = Bh + (size_t)(n0g + lrow) * DD + kk0 + lqh * 16;       \
        const __half* pbl = Bl + (size_t)(n0g + lrow) * DD + kk0 + lqh * 16;       \
        cpa16(dw,                       pah);                                      \
        cpa16(dw + 16u,                 pah + 8);                                  \
        cpa16(dw + PLANE*4u,            pal);                                      \
        cpa16(dw + PLANE*4u + 16u,      pal + 8);                                  \
        cpa16(dw + 2u*PLANE*4u,         pbh);                                      \
        cpa16(dw + 2u*PLANE*4u + 16u,   pbh + 8);                                  \
        cpa16(dw + 3u*PLANE*4u,         pbl);                                      \
        cpa16(dw + 3u*PLANE*4u + 16u,   pbl + 8);                                  \
    }

    ISSUE(0, 0);
    cpa_commit();

    for (int c = 0; c < NIT; ++c) {
        if (c + 1 < NIT) {
            ISSUE(c + 1, (c + 1) & 1);
            cpa_commit();
            asm volatile("cp.async.wait_group 1;" ::: "memory");
        } else {
            cpa_commit();
            asm volatile("cp.async.wait_group 0;" ::: "memory");
        }
        __syncthreads();

        const uint32_t sbase = smb + (uint32_t)(c & 1) * (STAGEF * 4u);

        #pragma unroll
        for (int s = 0; s < 2; ++s) {
            uint32_t ah[4][4], al[4][4];
            #pragma unroll
            for (int t = 0; t < 4; t++) {
                const uint32_t offA = (uint32_t)((m_off + t*16 + a_row) * RS + s*8 + a_k) * 4u;
                ldm4(ah[t], sbase + offA);
                ldm4(al[t], sbase + PLANE*4u + offA);
            }
            uint32_t bh[2][4], bl[2][4];
            #pragma unroll
            for (int u2 = 0; u2 < 2; u2++) {
                const uint32_t offB = (uint32_t)((n_off + u2*16 + b_row) * RS + s*8 + b_k) * 4u;
                ldm4(bh[u2], sbase + 2u*PLANE*4u + offB);
                ldm4(bl[u2], sbase + 3u*PLANE*4u + offB);
            }
            #pragma unroll
            for (int u2 = 0; u2 < 2; u2++)
                #pragma unroll
                for (int p = 0; p < 2; p++) {
                    const int u = u2 * 2 + p;
                    #pragma unroll
                    for (int t = 0; t < 4; t++) {
                        mma16(acc[t][u], ah[t], bh[u2][2*p], bh[u2][2*p+1]);
                        mma16(acc[t][u], ah[t], bl[u2][2*p], bl[u2][2*p+1]);
                        mma16(acc[t][u], al[t], bh[u2][2*p], bh[u2][2*p+1]);
                    }
                }
        }
        __syncthreads();
    }
    #undef ISSUE

    const bool hasb = (bias != nullptr);
    #pragma unroll
    for (int u = 0; u < 4; u++) {
        const int ncol = n0 + n_off + u * 8 + tig * 2;
        float2 bv = make_float2(0.f, 0.f);
        if (hasb) bv = *reinterpret_cast<const float2*>(bias + ncol);
        #pragma unroll
        for (int t = 0; t < 4; t++) {
            const int r = m0 + m_off + t * 16 + grp;
            *reinterpret_cast<float2*>(C + (size_t)r * DD + ncol) =
                make_float2(acc[t][u][0] + bv.x, acc[t][u][1] + bv.y);
            *reinterpret_cast<float2*>(C + (size_t)(r + 8) * DD + ncol) =
                make_float2(acc[t][u][2] + bv.x, acc[t][u][3] + bv.y);
        }
    }
}

// ---------------------------------------------------------------------------
// Causal flash attention, fp16 mma + ldmatrix (round-9 version, unchanged).
// ---------------------------------------------------------------------------
__global__ __launch_bounds__(256, 1)
void attn_mma(const float* __restrict__ gq, const float* __restrict__ gk,
              const float* __restrict__ gv, float* __restrict__ gc)
{
    extern __shared__ float smf[];
    float* Khi  = smf;
    float* Klo  = smf + 64*K36;
    float* Vthi = smf + 2*64*K36;
    float* Vtlo = smf + 3*64*K36;
    float* Ps   = smf + PSOFF;
    const uint32_t smb   = smem_u32(smf);
    const uint32_t aKhi  = smb;
    const uint32_t aKlo  = smb + 64u*K36*4u;
    const uint32_t aVthi = smb + 2u*64u*K36*4u;
    const uint32_t aVtlo = smb + 3u*64u*K36*4u;
    const uint32_t aPs   = smb + (uint32_t)PSOFF*4u;

    const int tid  = threadIdx.x;
    const int w    = tid >> 5, lane = tid & 31;
    const int grp  = lane >> 2, tig = lane & 3;
    const int wrow = w * 16;
    const int h    = blockIdx.y, b = blockIdx.z;
    const int st   = gridDim.x - 1 - blockIdx.x;
    const int s0   = st * TQ;

    const int a_row = lane & 15;
    const int a_k   = (lane >> 4) * 4;
    const int b_row = (lane & 7) + ((lane >> 1) & 8);
    const int b_k   = ((lane >> 3) & 1) * 4;

    const float* qb = gq + ((size_t)b * SS + s0) * DD + h * DKK;
    const float* kb = gk + (size_t)b * SS * DD + h * DKK;
    const float* vb = gv + (size_t)b * SS * DD + h * DKK;

    {
        float* Qlo = smf;
        #pragma unroll
        for (int u = 0; u < 4; u++) {
            int f = tid + u * 256;
            int row = f >> 3, oct = f & 7;
            float4 x0 = *reinterpret_cast<const float4*>(qb + (size_t)row * DD + oct * 8);
            float4 x1 = *reinterpret_cast<const float4*>(qb + (size_t)row * DD + oct * 8 + 4);
            uint4 hi, lo;
            split8(x0, x1, hi, lo);
            *reinterpret_cast<uint4*>(Ps  + row * K36 + oct * 4) = hi;
            *reinterpret_cast<uint4*>(Qlo + row * K36 + oct * 4) = lo;
        }
    }
    __syncthreads();
    uint32_t aqh[4][4], aql[4][4];
    #pragma unroll
    for (int ks = 0; ks < 4; ks++) {
        const uint32_t offQ = (uint32_t)((wrow + a_row) * K36 + ks*8 + a_k) * 4u;
        ldm4(aqh[ks], aPs + offQ);
        ldm4(aql[ks], smb + offQ);
    }
    __syncthreads();

    const int kr0 = tid >> 3, ko0 = tid & 7;
    const int kr1 = (tid + 256) >> 3;
    const int vl  = lane, vw8 = w * 8;
    float4 kreg[2][2], vreg[4];
    #pragma unroll
    for (int u = 0; u < 2; u++) {
        const int rr = u ? kr1 : kr0;
        kreg[u][0] = *reinterpret_cast<const float4*>(kb + (size_t)rr * DD + ko0 * 8);
        kreg[u][1] = *reinterpret_cast<const float4*>(kb + (size_t)rr * DD + ko0 * 8 + 4);
    }
    vreg[0] = *reinterpret_cast<const float4*>(vb + (size_t)(2*vl)   * DD + vw8);
    vreg[1] = *reinterpret_cast<const float4*>(vb + (size_t)(2*vl)   * DD + vw8 + 4);
    vreg[2] = *reinterpret_cast<const float4*>(vb + (size_t)(2*vl+1) * DD + vw8);
    vreg[3] = *reinterpret_cast<const float4*>(vb + (size_t)(2*vl+1) * DD + vw8 + 4);

    float m0r = -1e30f, m1r = -1e30f, l0 = 0.f, l1 = 0.f;
    float of[8][4];
    #pragma unroll
    for (int nt = 0; nt < 8; nt++)
        #pragma unroll
        for (int q = 0; q < 4; q++) of[nt][q] = 0.f;

    const int ntiles = s0 / TKV + 2;
    for (int tt = 0; tt < ntiles; ++tt) {
        #pragma unroll
        for (int u = 0; u < 2; u++) {
            const int rr = u ? kr1 : kr0;
            uint4 hi, lo;
            split8(kreg[u][0], kreg[u][1], hi, lo);
            *reinterpret_cast<uint4*>(Khi + rr * K36 + ko0 * 4) = hi;
            *reinterpret_cast<uint4*>(Klo + rr * K36 + ko0 * 4) = lo;
        }
        {
            const float* a0 = reinterpret_cast<const float*>(&vreg[0]);
            const float* a1 = reinterpret_cast<const float*>(&vreg[2]);
            #pragma unroll
            for (int j = 0; j < 8; j++) {
                float x = a0[j], y = a1[j];
                __half2 hh = __floats2half2_rn(x, y);
                float2 hf = __half22float2(hh);
                __half2 ll = __floats2half2_rn(x - hf.x, y - hf.y);
                Vthi[(vw8 + j) * K36 + vl] = __uint_as_float(*(uint32_t*)&hh);
                Vtlo[(vw8 + j) * K36 + vl] = __uint_as_float(*(uint32_t*)&ll);
            }
        }
        __syncthreads();

        if (tt + 1 < ntiles) {
            const int t0n = (tt + 1) * TKV;
            #pragma unroll
            for (int u = 0; u < 2; u++) {
                const int rr = (u ? kr1 : kr0) + t0n;
                kreg[u][0] = *reinterpret_cast<const float4*>(kb + (size_t)rr * DD + ko0 * 8);
                kreg[u][1] = *reinterpret_cast<const float4*>(kb + (size_t)rr * DD + ko0 * 8 + 4);
            }
            vreg[0] = *reinterpret_cast<const float4*>(vb + (size_t)(t0n+2*vl)   * DD + vw8);
            vreg[1] = *reinterpret_cast<const float4*>(vb + (size_t)(t0n+2*vl)   * DD + vw8 + 4);
            vreg[2] = *reinterpret_cast<const float4*>(vb + (size_t)(t0n+2*vl+1) * DD + vw8);
            vreg[3] = *reinterpret_cast<const float4*>(vb + (size_t)(t0n+2*vl+1) * DD + vw8 + 4);
        }

        float sf[8][4];
        #pragma unroll
        for (int nt = 0; nt < 8; nt++)
            #pragma unroll
            for (int q = 0; q < 4; q++) sf[nt][q] = 0.f;

        #pragma unroll
        for (int ks = 0; ks < 4; ks++) {
            #pragma unroll
            for (int nt2 = 0; nt2 < 4; nt2++) {
                const uint32_t offK = (uint32_t)((nt2*16 + b_row) * K36 + ks*8 + b_k) * 4u;
                uint32_t rh[4], rl[4];
                ldm4(rh, aKhi + offK);
                ldm4(rl, aKlo + offK);
                mma16(sf[2*nt2],   aqh[ks], rh[0], rh[1]);
                mma16(sf[2*nt2],   aql[ks], rh[0], rh[1]);
                mma16(sf[2*nt2],   aqh[ks], rl[0], rl[1]);
                mma16(sf[2*nt2+1], aqh[ks], rh[2], rh[3]);
                mma16(sf[2*nt2+1], aql[ks], rh[2], rh[3]);
                mma16(sf[2*nt2+1], aqh[ks], rl[2], rl[3]);
            }
        }

        const int t0 = tt * TKV;
        #pragma unroll
        for (int nt = 0; nt < 8; nt++)
            #pragma unroll
            for (int q = 0; q < 4; q++) sf[nt][q] *= 8.0f;
        if (t0 + TKV > s0) {
            const int r0g = s0 + wrow + grp, r1g = r0g + 8;
            #pragma unroll
            for (int nt = 0; nt < 8; nt++) {
                const int c0g = t0 + nt*8 + 2*tig;
                if (c0g     > r0g) sf[nt][0] = -1e30f;
                if (c0g + 1 > r0g) sf[nt][1] = -1e30f;
                if (c0g     > r1g) sf[nt][2] = -1e30f;
                if (c0g + 1 > r1g) sf[nt][3] = -1e30f;
            }
        }

        float mt0 = -1e30f, mt1 = -1e30f;
        #pragma unroll
        for (int nt = 0; nt < 8; nt++) {
            mt0 = fmaxf(mt0, fmaxf(sf[nt][0], sf[nt][1]));
            mt1 = fmaxf(mt1, fmaxf(sf[nt][2], sf[nt][3]));
        }
        mt0 = fmaxf(mt0, __shfl_xor_sync(0xffffffffu, mt0, 1));
        mt0 = fmaxf(mt0, __shfl_xor_sync(0xffffffffu, mt0, 2));
        mt1 = fmaxf(mt1, __shfl_xor_sync(0xffffffffu, mt1, 1));
        mt1 = fmaxf(mt1, __shfl_xor_sync(0xffffffffu, mt1, 2));

        const float mn0 = fmaxf(m0r, mt0), mn1 = fmaxf(m1r, mt1);
        const float a0s = __expf(m0r - mn0), a1s = __expf(m1r - mn1);
        m0r = mn0; m1r = mn1;

        float s0sum = 0.f, s1sum = 0.f;
        #pragma unroll
        for (int nt = 0; nt < 8; nt++) {
            float p0 = __expf(sf[nt][0] - mn0);
            float p1 = __expf(sf[nt][1] - mn0);
            float p2 = __expf(sf[nt][2] - mn1);
            float p3 = __expf(sf[nt][3] - mn1);
            s0sum += p0 + p1; s1sum += p2 + p3;
            __half2 hp0 = __floats2half2_rn(p0, p1);
            __half2 hp1 = __floats2half2_rn(p2, p3);
            Ps[(wrow + grp)     * K36 + nt*4 + tig] = __uint_as_float(*(uint32_t*)&hp0);
            Ps[(wrow + grp + 8) * K36 + nt*4 + tig] = __uint_as_float(*(uint32_t*)&hp1);
        }
        s0sum += __shfl_xor_sync(0xffffffffu, s0sum, 1);
        s0sum += __shfl_xor_sync(0xffffffffu, s0sum, 2);
        s1sum += __shfl_xor_sync(0xffffffffu, s1sum, 1);
        s1sum += __shfl_xor_sync(0xffffffffu, s1sum, 2);
        l0 = l0 * a0s + s0sum;
        l1 = l1 * a1s + s1sum;
        #pragma unroll
        for (int nt = 0; nt < 8; nt++) {
            of[nt][0] *= a0s; of[nt][1] *= a0s;
            of[nt][2] *= a1s; of[nt][3] *= a1s;
        }
        __syncwarp();

        #pragma unroll
        for (int ks = 0; ks < 4; ks++) {
            uint32_t ap[4];
            const uint32_t offP = (uint32_t)((wrow + a_row) * K36 + ks*8 + a_k) * 4u;
            ldm4(ap, aPs + offP);
            #pragma unroll
            for (int nt2 = 0; nt2 < 4; nt2++) {
                const uint32_t offV = (uint32_t)((nt2*16 + b_row) * K36 + ks*8 + b_k) * 4u;
                uint32_t rh[4], rl[4];
                ldm4(rh, aVthi + offV);
                ldm4(rl, aVtlo + offV);
                mma16(of[2*nt2],   ap, rh[0], rh[1]);
                mma16(of[2*nt2],   ap, rl[0], rl[1]);
                mma16(of[2*nt2+1], ap, rh[2], rh[3]);
                mma16(of[2*nt2+1], ap, rl[2], rl[3]);
            }
        }
        __syncthreads();
    }

    const float inv0 = 1.0f / l0, inv1 = 1.0f / l1;
    float* ob = gc + ((size_t)b * SS + s0 + wrow + grp) * DD + h * DKK;
    #pragma unroll
    for (int nt = 0; nt < 8; nt++) {
        const int col = nt*8 + 2*tig;
        *reinterpret_cast<float2*>(ob + col) =
            make_float2(of[nt][0] * inv0, of[nt][1] * inv0);
        *reinterpret_cast<float2*>(ob + (size_t)8 * DD + col) =
            make_float2(of[nt][2] * inv1, of[nt][3] * inv1);
    }
}

// ---------------------------------------------------------------------------
extern "C" void kernel_launch(void* const* d_in, const int* in_sizes, int n_in,
                              void* d_out, int out_size)
{
    const float* Q  = (const float*)d_in[0];
    const float* K  = (const float*)d_in[1];
    const float* V  = (const float*)d_in[2];
    // d_in[3] = causal mask (unused)
    const float* Wq = (const float*)d_in[4];
    const float* Wk = (const float*)d_in[5];
    const float* Wv = (const float*)d_in[6];
    const float* Wo = (const float*)d_in[7];
    const float* bo = (const float*)d_in[8];
    float* out = (float*)d_out;

    __half *xh, *xl, *wh, *wl;
    float *gq, *gk, *gv, *gc;
    cudaGetSymbolAddress((void**)&xh, g_xh);
    cudaGetSymbolAddress((void**)&xl, g_xl);
    cudaGetSymbolAddress((void**)&wh, g_wh);
    cudaGetSymbolAddress((void**)&wl, g_wl);
    cudaGetSymbolAddress((void**)&gq, g_q);
    cudaGetSymbolAddress((void**)&gk, g_k);
    cudaGetSymbolAddress((void**)&gv, g_v);
    cudaGetSymbolAddress((void**)&gc, g_c);

    cudaFuncSetAttribute(gemm_fp16, cudaFuncAttributeMaxDynamicSharedMemorySize, GEMM_SMEM);
    cudaFuncSetAttribute(attn_mma, cudaFuncAttributeMaxDynamicSharedMemorySize, ATTN_SMEM);

    const dim3 tg(DKK / 32, DD / 32, HH);     // (2, 32, 16)
    const int  na8 = NND / 8;                 // activation 8-float groups
    const int  nw8 = WSZ / 8;

    // pre-split inputs and weights to fp16 hi/lo planes
    split_half<<<na8/256, 256>>>((const float4*)Q, (uint4*)xh, (uint4*)xl, na8);
    split_half<<<na8/256, 256>>>((const float4*)K, (uint4*)(xh + NND), (uint4*)(xl + NND), na8);
    split_half<<<na8/256, 256>>>((const float4*)V, (uint4*)(xh + 2*NND), (uint4*)(xl + 2*NND), na8);
    transpose_split_w<<<tg, 256>>>(Wq, wh, wl);
    transpose_split_w<<<tg, 256>>>(Wk, wh + WSZ, wl + WSZ);
    transpose_split_w<<<tg, 256>>>(Wv, wh + 2*WSZ, wl + 2*WSZ);
    split_half<<<nw8/256, 256>>>((const float4*)Wo, (uint4*)(wh + 3*WSZ), (uint4*)(wl + 3*WSZ), nw8);

    // fused Q/K/V projections
    gemm_fp16<<<dim3(3 * DD / BN, NN / BM), 256, GEMM_SMEM>>>(
        xh, xl, wh, wl, nullptr, gq, gk, gv);

    attn_mma<<<dim3(SS/TQ, HH, BB), 256, ATTN_SMEM>>>(gq, gk, gv, gc);

    // split concat, then output projection
    split_half<<<na8/256, 256>>>((const float4*)gc, (uint4*)xh, (uint4*)xl, na8);
    gemm_fp16<<<dim3(DD / BN, NN / BM), 256, GEMM_SMEM>>>(
        xh, xl, wh + 3*WSZ, wl + 3*WSZ, bo, out, out, out);
}

// round 13
// speedup vs baseline: 1.0932x; 1.0932x over previous
#include <cuda_runtime.h>
#include <cuda_fp16.h>
#include <cstdint>

#define BB  4
#define SS  2048
#define DD  1024
#define HH  16
#define DKK 64
#define NN  (BB*SS)
#define NND (NN*DD)
#define WSZ (DD*DD)

// ---- fp16x3 warp-MMA GEMM tiling (round-9 mainloop) ----
#define BM   128
#define BN   128
#define BK   32
#define NIT  (DD/BK)            // 32
#define RS   20
#define PLANE (BM*RS)
#define STAGEF (4*PLANE)
#define GEMM_SMEM (2*STAGEF*4)  // 81920 bytes

// ---- attention tiling: double-buffered K/V, fp16 inputs ----
#define TQ   128
#define TKV  64
#define K36  36
#define KVW  (64*K36)           // 2304 words per plane
#define BUFW (4*KVW)            // 9216 words per buffer
#define PSW  (2*BUFW)           // Ps offset in words
#define ATTN_SMEM ((2*BUFW + 128*K36)*4)   // 92160 bytes

// scratch
__device__ float  g_wt[3][WSZ];   // K-major qkv weights (float)
__device__ __half g_xh[3*NND];    // q/k/v hi planes [B,S,H,DK]
__device__ __half g_xl[3*NND];    // q/k/v lo planes
__device__ float  g_c[NND];       // concat [B,S,D]

__device__ __forceinline__ uint32_t smem_u32(const void* p) {
    uint32_t a;
    asm("{ .reg .u64 t; cvta.to.shared.u64 t, %1; cvt.u32.u64 %0, t; }" : "=r"(a) : "l"(p));
    return a;
}
__device__ __forceinline__ void ldm4(uint32_t* r, uint32_t a) {
    asm volatile("ldmatrix.sync.aligned.m8n8.x4.shared.b16 {%0,%1,%2,%3}, [%4];"
        : "=r"(r[0]), "=r"(r[1]), "=r"(r[2]), "=r"(r[3]) : "r"(a));
}

// split 8 consecutive fp32 (two float4) into half2-packed hi/lo uint4s
__device__ __forceinline__ void split8(float4 p, float4 q, uint4& hi, uint4& lo) {
    __half2 h0 = __floats2half2_rn(p.x, p.y);
    __half2 h1 = __floats2half2_rn(p.z, p.w);
    __half2 h2v = __floats2half2_rn(q.x, q.y);
    __half2 h3 = __floats2half2_rn(q.z, q.w);
    float2 f0 = __half22float2(h0), f1 = __half22float2(h1);
    float2 f2 = __half22float2(h2v), f3 = __half22float2(h3);
    __half2 l0 = __floats2half2_rn(p.x - f0.x, p.y - f0.y);
    __half2 l1 = __floats2half2_rn(p.z - f1.x, p.w - f1.y);
    __half2 l2 = __floats2half2_rn(q.x - f2.x, q.y - f2.y);
    __half2 l3 = __floats2half2_rn(q.z - f3.x, q.w - f3.y);
    hi = make_uint4(*(uint32_t*)&h0, *(uint32_t*)&h1, *(uint32_t*)&h2v, *(uint32_t*)&h3);
    lo = make_uint4(*(uint32_t*)&l0, *(uint32_t*)&l1, *(uint32_t*)&l2, *(uint32_t*)&l3);
}

__device__ __forceinline__ void mma16(float* d, const uint32_t* a, uint32_t b0, uint32_t b1) {
    asm volatile("mma.sync.aligned.m16n8k16.row.col.f32.f16.f16.f32 "
        "{%0,%1,%2,%3},{%4,%5,%6,%7},{%8,%9},{%0,%1,%2,%3};"
        : "+f"(d[0]), "+f"(d[1]), "+f"(d[2]), "+f"(d[3])
        : "r"(a[0]), "r"(a[1]), "r"(a[2]), "r"(a[3]), "r"(b0), "r"(b1));
}

// ---------------------------------------------------------------------------
// Weight transpose: Wt[h*64+dk][d] = W[h][d][dk]
// ---------------------------------------------------------------------------
__global__ void transpose_w(const float* __restrict__ W, float* __restrict__ Wt) {
    __shared__ float t[32][33];
    const int h  = blockIdx.z;
    const int d0 = blockIdx.y << 5;
    const int k0 = blockIdx.x << 5;
    const int c  = threadIdx.x & 31;
    const int r4 = threadIdx.x >> 5;
    const float* Wh = W + ((size_t)h << 16);
    #pragma unroll
    for (int i = 0; i < 4; i++)
        t[r4 + 8*i][c] = Wh[(size_t)(d0 + r4 + 8*i) * DKK + k0 + c];
    __syncthreads();
    float* o = Wt + (size_t)(h * DKK + k0) * DD + d0;
    #pragma unroll
    for (int i = 0; i < 4; i++)
        o[(size_t)(r4 + 8*i) * DD + c] = t[c][r4 + 8*i];
}

// ---------------------------------------------------------------------------
// fp16x3 warp-MMA GEMM (round-9 mainloop). Epilogue: if Cf != nullptr write
// fp32 (+bias); else write fp16 hi/lo planes (Hhb/Hlb + seg*NND).
// ---------------------------------------------------------------------------
__global__ __launch_bounds__(256, 1)
void gemm_fp16(const float* __restrict__ A0, const float* __restrict__ A1,
               const float* __restrict__ A2, const float* __restrict__ Bw,
               const float* __restrict__ bias,
               float* __restrict__ Cf, __half* __restrict__ Hhb, __half* __restrict__ Hlb)
{
    extern __shared__ float sm[];
    const uint32_t smb = smem_u32(sm);
    const int tid  = threadIdx.x;
    const int m0   = blockIdx.y * BM;
    const int n0g  = blockIdx.x * BN;
    const int seg  = n0g >> 10;
    const int n0   = n0g & (DD - 1);
    const float* A = (seg == 0) ? A0 : (seg == 1) ? A1 : A2;

    const int w    = tid >> 5, lane = tid & 31;
    const int grp  = lane >> 2, tig = lane & 3;
    const int m_off = (w >> 2) * 64;
    const int n_off = (w & 3) * 32;

    const int a_row = lane & 15;
    const int a_k   = (lane >> 4) * 4;
    const int b_row = (lane & 7) + ((lane >> 1) & 8);
    const int b_k   = ((lane >> 3) & 1) * 4;

    const int r0l = tid >> 2, o0l = tid & 3;
    const int r1l = (tid + 256) >> 2;

    float acc[4][4][4];
    #pragma unroll
    for (int t = 0; t < 4; t++)
        #pragma unroll
        for (int u = 0; u < 4; u++)
            #pragma unroll
            for (int q = 0; q < 4; q++) acc[t][u][q] = 0.f;

    float4 ra[2][2], rb[2][2];
    #pragma unroll
    for (int u = 0; u < 2; u++) {
        const int rr = u ? r1l : r0l;
        ra[u][0] = *reinterpret_cast<const float4*>(A + (size_t)(m0 + rr) * DD + o0l * 8);
        ra[u][1] = *reinterpret_cast<const float4*>(A + (size_t)(m0 + rr) * DD + o0l * 8 + 4);
        rb[u][0] = *reinterpret_cast<const float4*>(Bw + (size_t)(n0g + rr) * DD + o0l * 8);
        rb[u][1] = *reinterpret_cast<const float4*>(Bw + (size_t)(n0g + rr) * DD + o0l * 8 + 4);
    }

    #define SPLIT_STORE(stage)                                                    \
    {                                                                             \
        float* AHI = sm + (stage) * STAGEF;                                       \
        float* ALO = AHI + PLANE;                                                 \
        float* BHI = AHI + 2 * PLANE;                                             \
        float* BLO = AHI + 3 * PLANE;                                             \
        uint4 hi, lo;                                                             \
        _Pragma("unroll")                                                         \
        for (int u = 0; u < 2; u++) {                                             \
            const int rr = u ? r1l : r0l;                                         \
            split8(ra[u][0], ra[u][1], hi, lo);                                   \
            *reinterpret_cast<uint4*>(AHI + rr*RS + o0l*4) = hi;                  \
            *reinterpret_cast<uint4*>(ALO + rr*RS + o0l*4) = lo;                  \
            split8(rb[u][0], rb[u][1], hi, lo);                                   \
            *reinterpret_cast<uint4*>(BHI + rr*RS + o0l*4) = hi;                  \
            *reinterpret_cast<uint4*>(BLO + rr*RS + o0l*4) = lo;                  \
        }                                                                         \
    }

    SPLIT_STORE(0);
    __syncthreads();

    for (int c = 0; c < NIT; ++c) {
        if (c + 1 < NIT) {
            const int k0 = (c + 1) * BK;
            #pragma unroll
            for (int u = 0; u < 2; u++) {
                const int rr = u ? r1l : r0l;
                ra[u][0] = *reinterpret_cast<const float4*>(A + (size_t)(m0 + rr) * DD + k0 + o0l * 8);
                ra[u][1] = *reinterpret_cast<const float4*>(A + (size_t)(m0 + rr) * DD + k0 + o0l * 8 + 4);
                rb[u][0] = *reinterpret_cast<const float4*>(Bw + (size_t)(n0g + rr) * DD + k0 + o0l * 8);
                rb[u][1] = *reinterpret_cast<const float4*>(Bw + (size_t)(n0g + rr) * DD + k0 + o0l * 8 + 4);
            }
        }

        const uint32_t sbase = smb + (uint32_t)(c & 1) * (STAGEF * 4u);

        #pragma unroll
        for (int s = 0; s < 2; ++s) {
            uint32_t ah[4][4], al[4][4];
            #pragma unroll
            for (int t = 0; t < 4; t++) {
                const uint32_t offA = (uint32_t)((m_off + t*16 + a_row) * RS + s*8 + a_k) * 4u;
                ldm4(ah[t], sbase + offA);
                ldm4(al[t], sbase + PLANE*4u + offA);
            }
            uint32_t bh[2][4], bl[2][4];
            #pragma unroll
            for (int u2 = 0; u2 < 2; u2++) {
                const uint32_t offB = (uint32_t)((n_off + u2*16 + b_row) * RS + s*8 + b_k) * 4u;
                ldm4(bh[u2], sbase + 2u*PLANE*4u + offB);
                ldm4(bl[u2], sbase + 3u*PLANE*4u + offB);
            }
            #pragma unroll
            for (int u2 = 0; u2 < 2; u2++)
                #pragma unroll
                for (int p = 0; p < 2; p++) {
                    const int u = u2 * 2 + p;
                    #pragma unroll
                    for (int t = 0; t < 4; t++) {
                        mma16(acc[t][u], ah[t], bh[u2][2*p], bh[u2][2*p+1]);
                        mma16(acc[t][u], ah[t], bl[u2][2*p], bl[u2][2*p+1]);
                        mma16(acc[t][u], al[t], bh[u2][2*p], bh[u2][2*p+1]);
                    }
                }
        }

        if (c + 1 < NIT) SPLIT_STORE((c + 1) & 1);
        __syncthreads();
    }
    #undef SPLIT_STORE

    if (Cf != nullptr) {
        #pragma unroll
        for (int u = 0; u < 4; u++) {
            const int ncol = n0 + n_off + u * 8 + tig * 2;
            float2 bv = *reinterpret_cast<const float2*>(bias + ncol);
            #pragma unroll
            for (int t = 0; t < 4; t++) {
                const int r = m0 + m_off + t * 16 + grp;
                *reinterpret_cast<float2*>(Cf + (size_t)r * DD + ncol) =
                    make_float2(acc[t][u][0] + bv.x, acc[t][u][1] + bv.y);
                *reinterpret_cast<float2*>(Cf + (size_t)(r + 8) * DD + ncol) =
                    make_float2(acc[t][u][2] + bv.x, acc[t][u][3] + bv.y);
            }
        }
    } else {
        __half* Hh = Hhb + (size_t)seg * NND;
        __half* Hl = Hlb + (size_t)seg * NND;
        #pragma unroll
        for (int u = 0; u < 4; u++) {
            const int ncol = n0 + n_off + u * 8 + tig * 2;
            #pragma unroll
            for (int t = 0; t < 4; t++) {
                const int r = m0 + m_off + t * 16 + grp;
                __half2 h0 = __floats2half2_rn(acc[t][u][0], acc[t][u][1]);
                float2  f0 = __half22float2(h0);
                __half2 l0 = __floats2half2_rn(acc[t][u][0] - f0.x, acc[t][u][1] - f0.y);
                *reinterpret_cast<__half2*>(Hh + (size_t)r * DD + ncol) = h0;
                *reinterpret_cast<__half2*>(Hl + (size_t)r * DD + ncol) = l0;
                __half2 h1 = __floats2half2_rn(acc[t][u][2], acc[t][u][3]);
                float2  f1 = __half22float2(h1);
                __half2 l1 = __floats2half2_rn(acc[t][u][2] - f1.x, acc[t][u][3] - f1.y);
                *reinterpret_cast<__half2*>(Hh + (size_t)(r + 8) * DD + ncol) = h1;
                *reinterpret_cast<__half2*>(Hl + (size_t)(r + 8) * DD + ncol) = l1;
            }
        }
    }
}

// ---------------------------------------------------------------------------
// Causal flash attention, fp16 mma + ldmatrix, fp16 hi/lo plane inputs,
// double-buffered K/V smem (ONE barrier per kv-tile).
// ---------------------------------------------------------------------------
__global__ __launch_bounds__(256, 1)
void attn_mma(const __half* __restrict__ qh, const __half* __restrict__ ql,
              const __half* __restrict__ kh, const __half* __restrict__ kl,
              const __half* __restrict__ vh, const __half* __restrict__ vl,
              float* __restrict__ gc)
{
    extern __shared__ float smf[];
    float* Ps = smf + PSW;
    const uint32_t smb = smem_u32(smf);
    const uint32_t aPs = smb + (uint32_t)PSW * 4u;

    const int tid  = threadIdx.x;
    const int w    = tid >> 5, lane = tid & 31;
    const int grp  = lane >> 2, tig = lane & 3;
    const int wrow = w * 16;
    const int h    = blockIdx.y, b = blockIdx.z;
    const int st   = gridDim.x - 1 - blockIdx.x;
    const int s0   = st * TQ;

    const int a_row = lane & 15;
    const int a_k   = (lane >> 4) * 4;
    const int b_row = (lane & 7) + ((lane >> 1) & 8);
    const int b_k   = ((lane >> 3) & 1) * 4;

    const size_t qoff = ((size_t)b * SS + s0) * DD + h * DKK;
    const size_t koff = (size_t)b * SS * DD + h * DKK;
    const __half* qhb = qh + qoff;
    const __half* qlb = ql + qoff;
    const __half* khb = kh + koff;
    const __half* klb = kl + koff;
    const __half* vhb = vh + koff;
    const __half* vlb = vl + koff;

    // K loader: 64 rows x 8 uint4; thread -> (row, 8-word span): TWO uint4 each
    const int krow = tid >> 2, kq = (tid & 3) * 8;    // kq = word offset in row
    const int vw8  = w * 8;                           // V cols per warp

    // prefetch K/V tile 0
    uint4 kh_r[2], kl_r[2], vh0_r, vh1_r, vl0_r, vl1_r;
    kh_r[0] = *reinterpret_cast<const uint4*>(khb + (size_t)krow * DD + kq * 2);
    kh_r[1] = *reinterpret_cast<const uint4*>(khb + (size_t)krow * DD + kq * 2 + 8);
    kl_r[0] = *reinterpret_cast<const uint4*>(klb + (size_t)krow * DD + kq * 2);
    kl_r[1] = *reinterpret_cast<const uint4*>(klb + (size_t)krow * DD + kq * 2 + 8);
    vh0_r = *reinterpret_cast<const uint4*>(vhb + (size_t)(2*lane)   * DD + vw8);
    vh1_r = *reinterpret_cast<const uint4*>(vhb + (size_t)(2*lane+1) * DD + vw8);
    vl0_r = *reinterpret_cast<const uint4*>(vlb + (size_t)(2*lane)   * DD + vw8);
    vl1_r = *reinterpret_cast<const uint4*>(vlb + (size_t)(2*lane+1) * DD + vw8);

    // ---- stage Q (hi->Ps, lo->buf0) and extract fragments ----
    #pragma unroll
    for (int u = 0; u < 4; u++) {
        int f = tid + u * 256;
        int row = f >> 3, oct = f & 7;
        *reinterpret_cast<uint4*>(Ps + row * K36 + oct * 4) =
            *reinterpret_cast<const uint4*>(qhb + (size_t)row * DD + oct * 8);
        *reinterpret_cast<uint4*>(smf + row * K36 + oct * 4) =
            *reinterpret_cast<const uint4*>(qlb + (size_t)row * DD + oct * 8);
    }
    __syncthreads();
    uint32_t aqh[4][4], aql[4][4];
    #pragma unroll
    for (int ks = 0; ks < 4; ks++) {
        const uint32_t offQ = (uint32_t)((wrow + a_row) * K36 + ks*8 + a_k) * 4u;
        ldm4(aqh[ks], aPs + offQ);
        ldm4(aql[ks], smb + offQ);
    }
    __syncthreads();

    #define KV_STORE(buf)                                                         \
    {                                                                             \
        float* Kh = smf + (buf) * BUFW;                                           \
        float* Kl = Kh + KVW;                                                     \
        uint32_t* Vh = reinterpret_cast<uint32_t*>(Kh + 2*KVW);                   \
        uint32_t* Vl = reinterpret_cast<uint32_t*>(Kh + 3*KVW);                   \
        *reinterpret_cast<uint4*>(Kh + krow * K36 + kq)     = kh_r[0];            \
        *reinterpret_cast<uint4*>(Kh + krow * K36 + kq + 4) = kh_r[1];            \
        *reinterpret_cast<uint4*>(Kl + krow * K36 + kq)     = kl_r[0];            \
        *reinterpret_cast<uint4*>(Kl + krow * K36 + kq + 4) = kl_r[1];            \
        _Pragma("unroll")                                                         \
        for (int j = 0; j < 8; j++) {                                             \
            const uint32_t sel = (j & 1) ? 0x7632u : 0x5410u;                     \
            Vh[(vw8 + j) * K36 + lane] = __byte_perm(                             \
                (&vh0_r.x)[j >> 1], (&vh1_r.x)[j >> 1], sel);                     \
            Vl[(vw8 + j) * K36 + lane] = __byte_perm(                             \
                (&vl0_r.x)[j >> 1], (&vl1_r.x)[j >> 1], sel);                     \
        }                                                                         \
    }

    KV_STORE(0);
    __syncthreads();

    float m0r = -1e30f, m1r = -1e30f, l0 = 0.f, l1 = 0.f;
    float of[8][4];
    #pragma unroll
    for (int nt = 0; nt < 8; nt++)
        #pragma unroll
        for (int q = 0; q < 4; q++) of[nt][q] = 0.f;

    const int ntiles = s0 / TKV + 2;
    for (int tt = 0; tt < ntiles; ++tt) {
        if (tt + 1 < ntiles) {
            const size_t t0n = (size_t)(tt + 1) * TKV;
            kh_r[0] = *reinterpret_cast<const uint4*>(khb + (t0n + krow) * DD + kq * 2);
            kh_r[1] = *reinterpret_cast<const uint4*>(khb + (t0n + krow) * DD + kq * 2 + 8);
            kl_r[0] = *reinterpret_cast<const uint4*>(klb + (t0n + krow) * DD + kq * 2);
            kl_r[1] = *reinterpret_cast<const uint4*>(klb + (t0n + krow) * DD + kq * 2 + 8);
            vh0_r = *reinterpret_cast<const uint4*>(vhb + (t0n + 2*lane)   * DD + vw8);
            vh1_r = *reinterpret_cast<const uint4*>(vhb + (t0n + 2*lane+1) * DD + vw8);
            vl0_r = *reinterpret_cast<const uint4*>(vlb + (t0n + 2*lane)   * DD + vw8);
            vl1_r = *reinterpret_cast<const uint4*>(vlb + (t0n + 2*lane+1) * DD + vw8);
        }

        const uint32_t aBuf  = smb + (uint32_t)(tt & 1) * (BUFW * 4u);
        const uint32_t aKhi  = aBuf;
        const uint32_t aKlo  = aBuf + KVW * 4u;
        const uint32_t aVthi = aBuf + 2u * KVW * 4u;
        const uint32_t aVtlo = aBuf + 3u * KVW * 4u;

        // ---- S = Q K^T (fp16 x3) ----
        float sf[8][4];
        #pragma unroll
        for (int nt = 0; nt < 8; nt++)
            #pragma unroll
            for (int q = 0; q < 4; q++) sf[nt][q] = 0.f;

        #pragma unroll
        for (int ks = 0; ks < 4; ks++) {
            #pragma unroll
            for (int nt2 = 0; nt2 < 4; nt2++) {
                const uint32_t offK = (uint32_t)((nt2*16 + b_row) * K36 + ks*8 + b_k) * 4u;
                uint32_t rh[4], rl[4];
                ldm4(rh, aKhi + offK);
                ldm4(rl, aKlo + offK);
                mma16(sf[2*nt2],   aqh[ks], rh[0], rh[1]);
                mma16(sf[2*nt2],   aql[ks], rh[0], rh[1]);
                mma16(sf[2*nt2],   aqh[ks], rl[0], rl[1]);
                mma16(sf[2*nt2+1], aqh[ks], rh[2], rh[3]);
                mma16(sf[2*nt2+1], aql[ks], rh[2], rh[3]);
                mma16(sf[2*nt2+1], aqh[ks], rl[2], rl[3]);
            }
        }

        const int t0 = tt * TKV;
        #pragma unroll
        for (int nt = 0; nt < 8; nt++)
            #pragma unroll
            for (int q = 0; q < 4; q++) sf[nt][q] *= 8.0f;
        if (t0 + TKV > s0) {
            const int r0g = s0 + wrow + grp, r1g = r0g + 8;
            #pragma unroll
            for (int nt = 0; nt < 8; nt++) {
                const int c0g = t0 + nt*8 + 2*tig;
                if (c0g     > r0g) sf[nt][0] = -1e30f;
                if (c0g + 1 > r0g) sf[nt][1] = -1e30f;
                if (c0g     > r1g) sf[nt][2] = -1e30f;
                if (c0g + 1 > r1g) sf[nt][3] = -1e30f;
            }
        }

        float mt0 = -1e30f, mt1 = -1e30f;
        #pragma unroll
        for (int nt = 0; nt < 8; nt++) {
            mt0 = fmaxf(mt0, fmaxf(sf[nt][0], sf[nt][1]));
            mt1 = fmaxf(mt1, fmaxf(sf[nt][2], sf[nt][3]));
        }
        mt0 = fmaxf(mt0, __shfl_xor_sync(0xffffffffu, mt0, 1));
        mt0 = fmaxf(mt0, __shfl_xor_sync(0xffffffffu, mt0, 2));
        mt1 = fmaxf(mt1, __shfl_xor_sync(0xffffffffu, mt1, 1));
        mt1 = fmaxf(mt1, __shfl_xor_sync(0xffffffffu, mt1, 2));

        const float mn0 = fmaxf(m0r, mt0), mn1 = fmaxf(m1r, mt1);
        const float a0s = __expf(m0r - mn0), a1s = __expf(m1r - mn1);
        m0r = mn0; m1r = mn1;

        float s0sum = 0.f, s1sum = 0.f;
        #pragma unroll
        for (int nt = 0; nt < 8; nt++) {
            float p0 = __expf(sf[nt][0] - mn0);
            float p1 = __expf(sf[nt][1] - mn0);
            float p2 = __expf(sf[nt][2] - mn1);
            float p3 = __expf(sf[nt][3] - mn1);
            s0sum += p0 + p1; s1sum += p2 + p3;
            __half2 hp0 = __floats2half2_rn(p0, p1);
            __half2 hp1 = __floats2half2_rn(p2, p3);
            Ps[(wrow + grp)     * K36 + nt*4 + tig] = __uint_as_float(*(uint32_t*)&hp0);
            Ps[(wrow + grp + 8) * K36 + nt*4 + tig] = __uint_as_float(*(uint32_t*)&hp1);
        }
        s0sum += __shfl_xor_sync(0xffffffffu, s0sum, 1);
        s0sum += __shfl_xor_sync(0xffffffffu, s0sum, 2);
        s1sum += __shfl_xor_sync(0xffffffffu, s1sum, 1);
        s1sum += __shfl_xor_sync(0xffffffffu, s1sum, 2);
        l0 = l0 * a0s + s0sum;
        l1 = l1 * a1s + s1sum;
        #pragma unroll
        for (int nt = 0; nt < 8; nt++) {
            of[nt][0] *= a0s; of[nt][1] *= a0s;
            of[nt][2] *= a1s; of[nt][3] *= a1s;
        }
        __syncwarp();

        // ---- O += P V ----
        #pragma unroll
        for (int ks = 0; ks < 4; ks++) {
            uint32_t ap[4];
            const uint32_t offP = (uint32_t)((wrow + a_row) * K36 + ks*8 + a_k) * 4u;
            ldm4(ap, aPs + offP);
            #pragma unroll
            for (int nt2 = 0; nt2 < 4; nt2++) {
                const uint32_t offV = (uint32_t)((nt2*16 + b_row) * K36 + ks*8 + b_k) * 4u;
                uint32_t rh[4], rl[4];
                ldm4(rh, aVthi + offV);
                ldm4(rl, aVtlo + offV);
                mma16(of[2*nt2],   ap, rh[0], rh[1]);
                mma16(of[2*nt2],   ap, rl[0], rl[1]);
                mma16(of[2*nt2+1], ap, rh[2], rh[3]);
                mma16(of[2*nt2+1], ap, rl[2], rl[3]);
            }
        }

        if (tt + 1 < ntiles) KV_STORE((tt + 1) & 1);
        __syncthreads();
    }
    #undef KV_STORE

    const float inv0 = 1.0f / l0, inv1 = 1.0f / l1;
    float* ob = gc + ((size_t)b * SS + s0 + wrow + grp) * DD + h * DKK;
    #pragma unroll
    for (int nt = 0; nt < 8; nt++) {
        const int col = nt*8 + 2*tig;
        *reinterpret_cast<float2*>(ob + col) =
            make_float2(of[nt][0] * inv0, of[nt][1] * inv0);
        *reinterpret_cast<float2*>(ob + (size_t)8 * DD + col) =
            make_float2(of[nt][2] * inv1, of[nt][3] * inv1);
    }
}

// ---------------------------------------------------------------------------
extern "C" void kernel_launch(void* const* d_in, const int* in_sizes, int n_in,
                              void* d_out, int out_size)
{
    const float* Q  = (const float*)d_in[0];
    const float* K  = (const float*)d_in[1];
    const float* V  = (const float*)d_in[2];
    // d_in[3] = causal mask (unused)
    const float* Wq = (const float*)d_in[4];
    const float* Wk = (const float*)d_in[5];
    const float* Wv = (const float*)d_in[6];
    const float* Wo = (const float*)d_in[7];
    const float* bo = (const float*)d_in[8];
    float* out = (float*)d_out;

    float *gwt, *gc;
    __half *xh, *xl;
    cudaGetSymbolAddress((void**)&gwt, g_wt);
    cudaGetSymbolAddress((void**)&xh,  g_xh);
    cudaGetSymbolAddress((void**)&xl,  g_xl);
    cudaGetSymbolAddress((void**)&gc,  g_c);

    cudaFuncSetAttribute(gemm_fp16, cudaFuncAttributeMaxDynamicSharedMemorySize, GEMM_SMEM);
    cudaFuncSetAttribute(attn_mma, cudaFuncAttributeMaxDynamicSharedMemorySize, ATTN_SMEM);

    const dim3 tg(DKK / 32, DD / 32, HH);     // (2, 32, 16)

    transpose_w<<<tg, 256>>>(Wq, gwt);
    transpose_w<<<tg, 256>>>(Wk, gwt + WSZ);
    transpose_w<<<tg, 256>>>(Wv, gwt + 2 * WSZ);

    // fused Q/K/V projections -> fp16 hi/lo planes
    gemm_fp16<<<dim3(3 * DD / BN, NN / BM), 256, GEMM_SMEM>>>(
        Q, K, V, gwt, nullptr, nullptr, xh, xl);

    attn_mma<<<dim3(SS/TQ, HH, BB), 256, ATTN_SMEM>>>(
        xh, xl, xh + NND, xl + NND, xh + 2*NND, xl + 2*NND, gc);

    // output projection: fp32 concat -> fp32 out (+bias)
    gemm_fp16<<<dim3(DD / BN, NN / BM), 256, GEMM_SMEM>>>(
        gc, gc, gc, Wo, bo, out, nullptr, nullptr);
}